// round 2
// baseline (speedup 1.0000x reference)
#include <cuda_runtime.h>

#define MAXN 4194304
#define NSH  16
#ifndef FLIP_E1
#define FLIP_E1 0
#endif

// ----------------------------- device scratch --------------------------------
__device__ double   g_acc[10];                 // n, s0..s2, s00,s01,s02,s11,s12,s22
__device__ unsigned g_h1[2][NSH][65536];       // level-1 sharded hists (2 key rows)
__device__ unsigned g_h2[4][65536];            // level-2 hists (4 selection slots)
__device__ unsigned g_keys[2u * MAXN];

struct SelState {
    long long rank[4];
    int       histidx[4];
    int       bin[4];
    long long rem[4];
    float     val[4];
    float     fracA, fracB;
    double    e1[3], e2[3];
    double    M[2][3];
};
__device__ SelState g_sel;
__device__ float    g_W[9];

// ------------------------------- helpers -------------------------------------
__device__ __forceinline__ unsigned key_of(float x) {
    unsigned u = __float_as_uint(x);
    return (u & 0x80000000u) ? ~u : (u | 0x80000000u);
}
__device__ __forceinline__ float val_of(unsigned k) {
    unsigned u = (k & 0x80000000u) ? (k ^ 0x80000000u) : ~k;
    return __uint_as_float(u);
}
__device__ __forceinline__ void load_od(const float* __restrict__ img, int j, int N,
                                        float od[3], bool& m) {
    float i0 = __ldg(img + j);
    float i1 = __ldg(img + j + N);
    float i2 = __ldg(img + j + 2 * N);
    od[0] = -logf((floorf(i0 * 255.0f) + 1.0f) / 240.0f);
    od[1] = -logf((floorf(i1 * 255.0f) + 1.0f) / 240.0f);
    od[2] = -logf((floorf(i2 * 255.0f) + 1.0f) / 240.0f);
    m = (od[0] >= 0.15f) && (od[1] >= 0.15f) && (od[2] >= 0.15f);
}

// ------------------------------- clears --------------------------------------
__global__ void k_clear1() {
    int i = blockIdx.x * blockDim.x + threadIdx.x;
    const int total = 2 * NSH * 65536;
    unsigned* p = &g_h1[0][0][0];
    for (int k = i; k < total; k += gridDim.x * blockDim.x) p[k] = 0u;
    if (i < 10) g_acc[i] = 0.0;
}
__global__ void k_clear2() {
    int i = blockIdx.x * blockDim.x + threadIdx.x;
    const int total = 4 * 65536;
    unsigned* p = &g_h2[0][0];
    for (int k = i; k < total; k += gridDim.x * blockDim.x) p[k] = 0u;
}

// ------------------------------- pass 1: covariance --------------------------
__global__ void k_cov(const float* __restrict__ img, int N) {
    double a[10];
#pragma unroll
    for (int i = 0; i < 10; i++) a[i] = 0.0;
    for (int j = blockIdx.x * blockDim.x + threadIdx.x; j < N; j += gridDim.x * blockDim.x) {
        float od[3]; bool m;
        load_od(img, j, N, od, m);
        if (m) {
            double o0 = od[0], o1 = od[1], o2 = od[2];
            a[0] += 1.0;
            a[1] += o0; a[2] += o1; a[3] += o2;
            a[4] += o0 * o0; a[5] += o0 * o1; a[6] += o0 * o2;
            a[7] += o1 * o1; a[8] += o1 * o2; a[9] += o2 * o2;
        }
    }
#pragma unroll
    for (int i = 0; i < 10; i++)
        for (int o = 16; o; o >>= 1) a[i] += __shfl_xor_sync(0xffffffffu, a[i], o);
    __shared__ double sm[8][10];
    int lane = threadIdx.x & 31, wid = threadIdx.x >> 5;
    if (lane == 0)
        for (int i = 0; i < 10; i++) sm[wid][i] = a[i];
    __syncthreads();
    if (threadIdx.x < 10) {
        double s = 0.0;
        int nw = blockDim.x >> 5;
        for (int w = 0; w < nw; w++) s += sm[w][threadIdx.x];
        atomicAdd(&g_acc[threadIdx.x], s);
    }
}

// ------------------------- eigensolver + phi quantile ranks ------------------
__global__ void k_eig() {
    double n = g_acc[0];
    double m0 = g_acc[1] / n, m1 = g_acc[2] / n, m2 = g_acc[3] / n;
    double A[3][3];
    A[0][0] = (g_acc[4] - n * m0 * m0) / (n - 1.0);
    A[0][1] = (g_acc[5] - n * m0 * m1) / (n - 1.0);
    A[0][2] = (g_acc[6] - n * m0 * m2) / (n - 1.0);
    A[1][1] = (g_acc[7] - n * m1 * m1) / (n - 1.0);
    A[1][2] = (g_acc[8] - n * m1 * m2) / (n - 1.0);
    A[2][2] = (g_acc[9] - n * m2 * m2) / (n - 1.0);
    A[1][0] = A[0][1]; A[2][0] = A[0][2]; A[2][1] = A[1][2];
    double V[3][3] = {{1,0,0},{0,1,0},{0,0,1}};
    for (int sweep = 0; sweep < 60; sweep++) {
        double off = A[0][1]*A[0][1] + A[0][2]*A[0][2] + A[1][2]*A[1][2];
        if (off < 1e-28) break;
        for (int p = 0; p < 2; p++)
            for (int q = p + 1; q < 3; q++) {
                double apq = A[p][q];
                if (fabs(apq) < 1e-300) continue;
                double th = (A[q][q] - A[p][p]) / (2.0 * apq);
                double t = ((th >= 0.0) ? 1.0 : -1.0) / (fabs(th) + sqrt(th * th + 1.0));
                double c = 1.0 / sqrt(t * t + 1.0), s = t * c;
                for (int k = 0; k < 3; k++) {
                    double akp = A[k][p], akq = A[k][q];
                    A[k][p] = c * akp - s * akq;
                    A[k][q] = s * akp + c * akq;
                }
                for (int k = 0; k < 3; k++) {
                    double apk = A[p][k], aqk = A[q][k];
                    A[p][k] = c * apk - s * aqk;
                    A[q][k] = s * apk + c * aqk;
                }
                for (int k = 0; k < 3; k++) {
                    double vkp = V[k][p], vkq = V[k][q];
                    V[k][p] = c * vkp - s * vkq;
                    V[k][q] = s * vkp + c * vkq;
                }
            }
    }
    double w[3] = {A[0][0], A[1][1], A[2][2]};
    int idx[3] = {0, 1, 2};
    if (w[idx[0]] > w[idx[1]]) { int t = idx[0]; idx[0] = idx[1]; idx[1] = t; }
    if (w[idx[1]] > w[idx[2]]) { int t = idx[1]; idx[1] = idx[2]; idx[2] = t; }
    if (w[idx[0]] > w[idx[1]]) { int t = idx[0]; idx[0] = idx[1]; idx[1] = t; }
    double e1[3], e2[3];
    for (int k = 0; k < 3; k++) { e1[k] = V[k][idx[1]]; e2[k] = V[k][idx[2]]; }
    {   // canonicalize middle eigvec sign (the only sign that matters)
        int im = 0;
        if (fabs(e1[1]) > fabs(e1[im])) im = 1;
        if (fabs(e1[2]) > fabs(e1[im])) im = 2;
        double sg = (e1[im] < 0.0) ? -1.0 : 1.0;
#if FLIP_E1
        sg = -sg;
#endif
        for (int k = 0; k < 3; k++) e1[k] *= sg;
    }
    {   // largest eigvec sign is provably irrelevant; canonicalize anyway
        int im = 0;
        if (fabs(e2[1]) > fabs(e2[im])) im = 1;
        if (fabs(e2[2]) > fabs(e2[im])) im = 2;
        if (e2[im] < 0.0)
            for (int k = 0; k < 3; k++) e2[k] = -e2[k];
    }
    for (int k = 0; k < 3; k++) { g_sel.e1[k] = e1[k]; g_sel.e2[k] = e2[k]; }
    long long ni = (long long)(n + 0.5);
    float nf = (float)(ni - 1);
    float p1 = 0.01f * nf;
    float p2 = 0.99f * nf;
    g_sel.rank[0] = (long long)floorf(p1);
    g_sel.rank[1] = (long long)ceilf(p1);
    g_sel.fracA   = p1 - floorf(p1);
    g_sel.rank[2] = (long long)floorf(p2);
    g_sel.rank[3] = (long long)ceilf(p2);
    g_sel.fracB   = p2 - floorf(p2);
    for (int s = 0; s < 4; s++) g_sel.histidx[s] = 0;
}

// ------------------------ phi keys + level-1 histogram -----------------------
__global__ void k_phi(const float* __restrict__ img, int N) {
    int j = blockIdx.x * blockDim.x + threadIdx.x;
    if (j >= N) return;
    float od[3]; bool m;
    load_od(img, j, N, od, m);
    unsigned key = 0xFFFFFFFFu;               // unmasked -> +inf region
    if (m) {
        float e10 = (float)g_sel.e1[0], e11 = (float)g_sel.e1[1], e12 = (float)g_sel.e1[2];
        float e20 = (float)g_sel.e2[0], e21 = (float)g_sel.e2[1], e22 = (float)g_sel.e2[2];
        float t0 = od[0] * e10 + od[1] * e11 + od[2] * e12;
        float t1 = od[0] * e20 + od[1] * e21 + od[2] * e22;
        float phi = atan2f(t1, t0);
        key = key_of(phi);
        atomicAdd(&g_h1[0][blockIdx.x & (NSH - 1)][key >> 16], 1u);
    }
    g_keys[j] = key;
}

// ------------------------------ shard reduction ------------------------------
__global__ void k_sumsh() {
    int i = blockIdx.x * blockDim.x + threadIdx.x;
    if (i >= 2 * 65536) return;
    int r = i >> 16, b = i & 65535;
    unsigned s = 0;
#pragma unroll
    for (int sh = 0; sh < NSH; sh++) s += g_h1[r][sh][b];
    g_h1[r][0][b] = s;
}

// --------------------------- exact rank selection ----------------------------
__global__ void k_select(int low) {
    int s = blockIdx.x;
    const unsigned* h;
    long long rank;
    if (low) { h = g_h2[s];                   rank = g_sel.rem[s]; }
    else     { h = g_h1[g_sel.histidx[s]][0]; rank = g_sel.rank[s]; }
    __shared__ unsigned long long ps[1024];
    int t = threadIdx.x;
    unsigned long long sum = 0;
#pragma unroll 8
    for (int i = 0; i < 64; i++) sum += h[t * 64 + i];
    ps[t] = sum;
    __syncthreads();
    for (int o = 1; o < 1024; o <<= 1) {
        unsigned long long v = (t >= o) ? ps[t - o] : 0ull;
        __syncthreads();
        ps[t] += v;
        __syncthreads();
    }
    unsigned long long excl = t ? ps[t - 1] : 0ull;
    unsigned long long incl = ps[t];
    if ((unsigned long long)rank >= excl && (unsigned long long)rank < incl) {
        unsigned long long c = excl;
        for (int i = 0; i < 64; i++) {
            unsigned hv = h[t * 64 + i];
            if ((unsigned long long)rank < c + hv) {
                int b = t * 64 + i;
                if (!low) { g_sel.bin[s] = b; g_sel.rem[s] = rank - (long long)c; }
                else {
                    unsigned key = ((unsigned)g_sel.bin[s] << 16) | (unsigned)b;
                    g_sel.val[s] = val_of(key);
                }
                break;
            }
            c += hv;
        }
    }
}

// ------------------------------ level-2 histogram ----------------------------
__global__ void k_histlow(int N, int phaseC) {
    int j = blockIdx.x * blockDim.x + threadIdx.x;
    if (j >= N) return;
    if (!phaseC) {
        unsigned k = g_keys[j];
        unsigned t = k >> 16;
#pragma unroll
        for (int s = 0; s < 4; s++)
            if (t == (unsigned)g_sel.bin[s]) atomicAdd(&g_h2[s][k & 65535u], 1u);
    } else {
        unsigned k0 = g_keys[j], k1 = g_keys[MAXN + j];
        unsigned t0 = k0 >> 16, t1 = k1 >> 16;
        if (t0 == (unsigned)g_sel.bin[0]) atomicAdd(&g_h2[0][k0 & 65535u], 1u);
        if (t0 == (unsigned)g_sel.bin[1]) atomicAdd(&g_h2[1][k0 & 65535u], 1u);
        if (t1 == (unsigned)g_sel.bin[2]) atomicAdd(&g_h2[2][k1 & 65535u], 1u);
        if (t1 == (unsigned)g_sel.bin[3]) atomicAdd(&g_h2[3][k1 & 65535u], 1u);
    }
}

// ------------------------ HE, M = (HE^T HE)^-1 HE^T, C ranks -----------------
__global__ void k_finphi(int N) {
    float minPhi = g_sel.val[0] * (1.0f - g_sel.fracA) + g_sel.val[1] * g_sel.fracA;
    float maxPhi = g_sel.val[2] * (1.0f - g_sel.fracB) + g_sel.val[3] * g_sel.fracB;
    float e1f[3], e2f[3];
    for (int k = 0; k < 3; k++) { e1f[k] = (float)g_sel.e1[k]; e2f[k] = (float)g_sel.e2[k]; }
    float cn = cosf(minPhi), sn = sinf(minPhi);
    float cx = cosf(maxPhi), sx = sinf(maxPhi);
    float vMin[3], vMax[3];
    for (int k = 0; k < 3; k++) {
        vMin[k] = e1f[k] * cn + e2f[k] * sn;
        vMax[k] = e1f[k] * cx + e2f[k] * sx;
    }
    bool sel = vMin[0] > vMax[0];
    float h1v[3], h2v[3];
    for (int k = 0; k < 3; k++) {
        h1v[k] = sel ? vMin[k] : vMax[k];
        h2v[k] = sel ? vMax[k] : vMin[k];
    }
    double A00 = 0, A01 = 0, A11 = 0;
    for (int k = 0; k < 3; k++) {
        A00 += (double)h1v[k] * h1v[k];
        A01 += (double)h1v[k] * h2v[k];
        A11 += (double)h2v[k] * h2v[k];
    }
    double det = A00 * A11 - A01 * A01;
    for (int k = 0; k < 3; k++) {
        g_sel.M[0][k] = (A11 * (double)h1v[k] - A01 * (double)h2v[k]) / det;
        g_sel.M[1][k] = (A00 * (double)h2v[k] - A01 * (double)h1v[k]) / det;
    }
    float nf = (float)(N - 1);
    float p = 0.99f * nf;
    g_sel.rank[0] = (long long)floorf(p);
    g_sel.rank[1] = (long long)ceilf(p);
    g_sel.fracA   = p - floorf(p);
    g_sel.rank[2] = g_sel.rank[0];
    g_sel.rank[3] = g_sel.rank[1];
    g_sel.fracB   = g_sel.fracA;
    g_sel.histidx[0] = 0; g_sel.histidx[1] = 0;
    g_sel.histidx[2] = 1; g_sel.histidx[3] = 1;
}

// ---------------------------- C keys + histograms ----------------------------
__global__ void k_C(const float* __restrict__ img, int N) {
    int j = blockIdx.x * blockDim.x + threadIdx.x;
    if (j >= N) return;
    float od[3]; bool m;
    load_od(img, j, N, od, m);
    float M00 = (float)g_sel.M[0][0], M01 = (float)g_sel.M[0][1], M02 = (float)g_sel.M[0][2];
    float M10 = (float)g_sel.M[1][0], M11 = (float)g_sel.M[1][1], M12 = (float)g_sel.M[1][2];
    float c0 = M00 * od[0] + M01 * od[1] + M02 * od[2];
    float c1 = M10 * od[0] + M11 * od[1] + M12 * od[2];
    unsigned k0 = key_of(c0), k1 = key_of(c1);
    g_keys[j] = k0;
    g_keys[MAXN + j] = k1;
    int sh = blockIdx.x & (NSH - 1);
    atomicAdd(&g_h1[0][sh][k0 >> 16], 1u);
    atomicAdd(&g_h1[1][sh][k1 >> 16], 1u);
}

// ------------------------------- final scalars -------------------------------
__global__ void k_finC(const float* __restrict__ HERef, const float* __restrict__ mcr) {
    float maxC0 = g_sel.val[0] * (1.0f - g_sel.fracA) + g_sel.val[1] * g_sel.fracA;
    float maxC1 = g_sel.val[2] * (1.0f - g_sel.fracB) + g_sel.val[3] * g_sel.fracB;
    float s0 = mcr[0] / maxC0;
    float s1 = mcr[1] / maxC1;
    for (int c = 0; c < 3; c++)
        for (int k = 0; k < 3; k++)
            g_W[c * 3 + k] = (float)((double)HERef[c * 2 + 0] * (double)s0 * g_sel.M[0][k]
                                   + (double)HERef[c * 2 + 1] * (double)s1 * g_sel.M[1][k]);
}

// -------------------------------- output pass --------------------------------
__global__ void k_out(const float* __restrict__ img, float* __restrict__ out, int N) {
    int j = blockIdx.x * blockDim.x + threadIdx.x;
    if (j >= N) return;
    float od[3]; bool m;
    load_od(img, j, N, od, m);
    float w[9];
#pragma unroll
    for (int i = 0; i < 9; i++) w[i] = g_W[i];
#pragma unroll
    for (int c = 0; c < 3; c++) {
        float a = w[c * 3 + 0] * od[0] + w[c * 3 + 1] * od[1] + w[c * 3 + 2] * od[2];
        float v = fminf(240.0f * expf(-a), 255.0f);
        out[j * 3 + c] = floorf(v) * (1.0f / 255.0f);
    }
}

// --------------------------------- launcher ----------------------------------
extern "C" void kernel_launch(void* const* d_in, const int* in_sizes, int n_in,
                              void* d_out, int out_size) {
    const float* img   = (const float*)d_in[0];
    const float* HERef = (const float*)d_in[1];
    const float* mcr   = (const float*)d_in[2];
    float* out = (float*)d_out;
    int N = in_sizes[0] / 3;
    int B = 256;
    int G = (N + B - 1) / B;

    // --- phi phase ---
    k_clear1<<<512, 256>>>();
    k_cov<<<1024, 256>>>(img, N);
    k_eig<<<1, 1>>>();
    k_phi<<<G, B>>>(img, N);
    k_sumsh<<<(2 * 65536 + 255) / 256, 256>>>();
    k_select<<<4, 1024>>>(0);
    k_clear2<<<256, 256>>>();
    k_histlow<<<G, B>>>(N, 0);
    k_select<<<4, 1024>>>(1);
    k_finphi<<<1, 1>>>(N);

    // --- C phase ---
    k_clear1<<<512, 256>>>();
    k_C<<<G, B>>>(img, N);
    k_sumsh<<<(2 * 65536 + 255) / 256, 256>>>();
    k_select<<<4, 1024>>>(0);
    k_clear2<<<256, 256>>>();
    k_histlow<<<G, B>>>(N, 1);
    k_select<<<4, 1024>>>(1);
    k_finC<<<1, 1>>>(HERef, mcr);

    // --- output ---
    k_out<<<G, B>>>(img, out, N);
}